// round 16
// baseline (speedup 1.0000x reference)
#include <cuda_runtime.h>

// Problem shape (fixed by the dataset): B=4, S=4096, D=2048, W=4
#define BV 4
#define SV 4096
#define DV 2048
#define TOK 32            // tokens per score block
#define NROWS 35          // real rows (3-row causal halo)
#define NGROUP 10         // 4-row TMA groups (rows 0..39, 36..39 pad)
#define THREADS 512       // 4 channels/thread

// Scratch (no allocations allowed) ------------------------------------------
__device__ int      g_mask[BV * SV];
__device__ int      g_src [BV * SV];
__device__ unsigned g_done[BV];      // monotonic across graph replays

// Packed f32x2 helpers --------------------------------------------------------
typedef unsigned long long u64;
static __device__ __forceinline__ u64 pk(float lo, float hi) {
    u64 r; asm("mov.b64 %0,{%1,%2};" : "=l"(r) : "f"(lo), "f"(hi)); return r;
}
static __device__ __forceinline__ void upk(u64 v, float& lo, float& hi) {
    asm("mov.b64 {%0,%1},%2;" : "=f"(lo), "=f"(hi) : "l"(v));
}
static __device__ __forceinline__ u64 f2fma(u64 a, u64 b, u64 c) {
    u64 d; asm("fma.rn.f32x2 %0,%1,%2,%3;" : "=l"(d) : "l"(a), "l"(b), "l"(c)); return d;
}
static __device__ __forceinline__ u64 f2mul(u64 a, u64 b) {
    u64 d; asm("mul.rn.f32x2 %0,%1,%2;" : "=l"(d) : "l"(a), "l"(b)); return d;
}

static __device__ __forceinline__ float warp_sum(float v) {
#pragma unroll
    for (int o = 16; o > 0; o >>= 1)
        v += __shfl_xor_sync(0xffffffffu, v, o);
    return v;
}

// Bulk-copy + mbarrier helpers ------------------------------------------------
static __device__ __forceinline__ unsigned smem_u32(const void* p) {
    unsigned long long g;
    asm("cvta.to.shared.u64 %0, %1;" : "=l"(g) : "l"(p));
    return (unsigned)g;
}
static __device__ __forceinline__ void mbar_init(unsigned mbar, unsigned cnt) {
    asm volatile("mbarrier.init.shared.b64 [%0], %1;" :: "r"(mbar), "r"(cnt)
                 : "memory");
}
static __device__ __forceinline__ void mbar_expect_tx(unsigned mbar,
                                                      unsigned bytes) {
    asm volatile("mbarrier.arrive.expect_tx.shared.b64 _, [%0], %1;"
                 :: "r"(mbar), "r"(bytes) : "memory");
}
static __device__ __forceinline__ void mbar_wait(unsigned mbar,
                                                 unsigned parity) {
    asm volatile(
        "{\n\t.reg .pred P;\n\t"
        "WAIT_%=:\n\t"
        "mbarrier.try_wait.parity.acquire.cta.shared::cta.b64 P, [%0], %1, 0x989680;\n\t"
        "@!P bra WAIT_%=;\n\t"
        "}"
        :: "r"(mbar), "r"(parity) : "memory");
}
static __device__ __forceinline__ void bulk_g2s(unsigned dst, const void* src,
                                                unsigned mbar) {
    asm volatile(
        "cp.async.bulk.shared::cluster.global.mbarrier::complete_tx::bytes "
        "[%0], [%1], %2, [%3];"
        :: "r"(dst), "l"(src), "r"(8192u), "r"(mbar) : "memory");
}
static __device__ __forceinline__ void sts_zero16(unsigned dst) {
    asm volatile("st.shared.v4.b32 [%0],{%1,%1,%1,%1};" :: "r"(dst), "r"(0));
}

// Sum of 4 silu-gated terms with ONE reciprocal
static __device__ __forceinline__ float silu4(
    float v0, float v1, float v2, float v3,
    float g0, float g1, float g2, float g3)
{
    float d0 = 1.f + __expf(-v0);
    float d1 = 1.f + __expf(-v1);
    float d2 = 1.f + __expf(-v2);
    float d3 = 1.f + __expf(-v3);
    float a0 = g0 * v0, a1 = g1 * v1, a2 = g2 * v2, a3 = g3 * v3;
    float n01 = fmaf(a0, d1, a1 * d0);
    float n23 = fmaf(a2, d3, a3 * d2);
    float D01 = d0 * d1;
    float D23 = d2 * d3;
    float n = fmaf(n01, D23, n23 * D01);
    float D = D01 * D23;
    return __fdividef(n, D);
}

// Issue a 4-row TMA group. GB = (4g) % 12 compile-time; mbar = GB/4.
template<int GB>
static __device__ __forceinline__ void issue4(int g, int s0,
                                              unsigned ring_u32,
                                              unsigned mbar_u32,
                                              const float* xrow) {
    if (g >= NGROUP) return;
    const unsigned mbar = mbar_u32 + (GB / 4) * 8;
    int cnt = 0;
#pragma unroll
    for (int k = 0; k < 4; k++) {
        const int i = 4 * g + k;
        if (i < NROWS && (s0 - 3 + i) >= 0) cnt++;
    }
    mbar_expect_tx(mbar, (unsigned)cnt * 8192u);
#pragma unroll
    for (int k = 0; k < 4; k++) {
        const int i = 4 * g + k;
        if (i < NROWS && (s0 - 3 + i) >= 0)
            bulk_g2s(ring_u32 + (unsigned)((GB + k) * 8192),
                     xrow + (size_t)(s0 - 3 + i) * DV, mbar);
    }
}

// One 8-row chunk (512 threads, 4 ch/thread). CB = (8c)%12 in {0,8,4}.
// Mid-chunk TMA issue (after k=3) keeps the odd group half a chunk ahead.
template<int CB, bool FIRST, bool LAST>
static __device__ __forceinline__ void process_chunk(
    int c, int s0, int tid, int lane, int wid,
    const float4* ring, unsigned ring_u32, unsigned mbar_u32,
    const float* xrow, u64 (&acc2)[4][2], const u64 (&wnv2)[4][2],
    const float (&gch)[4], float* rinv_s, float (*pbuf)[64])
{
    constexpr int M0 = (CB == 0) ? 0 : ((CB == 8) ? 2 : 1);   // (2c)%3
    constexpr int M1 = (CB == 0) ? 1 : ((CB == 8) ? 0 : 2);   // (2c+1)%3
    {
        const int g0 = 2 * c, g1 = 2 * c + 1;
        mbar_wait(mbar_u32 + M0 * 8, (unsigned)((g0 / 3) & 1));
        mbar_wait(mbar_u32 + M1 * 8, (unsigned)((g1 / 3) & 1));
    }

    // ---- Phase A: warp-per-row rinv, FFMA2 x2-accumulator sumsq
    if (wid < (LAST ? 3 : 8)) {
        int slot = CB + wid; if (slot >= 12) slot -= 12;
        const float4* rowp = ring + slot * 512;
        u64 sa = 0ull, sb = 0ull;
#pragma unroll
        for (int j = 0; j < 16; j++) {
            const float4 v = rowp[lane + 32 * j];
            const u64 p0 = pk(v.x, v.y), p1 = pk(v.z, v.w);
            sa = f2fma(p0, p0, sa);
            sb = f2fma(p1, p1, sb);
        }
        float a0, a1, b0, b1;
        upk(sa, a0, a1); upk(sb, b0, b1);
        float ss = (a0 + a1) + (b0 + b1);
        ss = warp_sum(ss);
        if (lane == 0) rinv_s[wid] = rsqrtf(ss * (1.f / DV) + 1e-5f);
    }
    __syncthreads();

    float rv[8];
    {
        const float4 r0 = *(const float4*)rinv_s;
        const float4 r1 = *(const float4*)(rinv_s + 4);
        rv[0] = r0.x; rv[1] = r0.y; rv[2] = r0.z; rv[3] = r0.w;
        rv[4] = r1.x; rv[5] = r1.y; rv[6] = r1.z; rv[7] = r1.w;
    }

    // ---- Phase B: branch-free conv/silu/dot (slots compile-time)
#pragma unroll
    for (int k = 0; k < 8; k++) {
        const float4 a = ring[((CB + k) % 12) * 512 + tid];
        const u64 ri2 = pk(rv[k], rv[k]);
        u64 xr2[2] = { f2mul(ri2, pk(a.x, a.y)), f2mul(ri2, pk(a.z, a.w)) };

#pragma unroll
        for (int j = 0; j < 2; j++)          // tap0 OVERWRITES (no resets)
            acc2[k & 3][j] = f2mul(wnv2[0][j], xr2[j]);
#pragma unroll
        for (int j = 0; j < 2; j++)
            acc2[(k + 3) & 3][j] = f2fma(wnv2[1][j], xr2[j], acc2[(k + 3) & 3][j]);
#pragma unroll
        for (int j = 0; j < 2; j++)
            acc2[(k + 2) & 3][j] = f2fma(wnv2[2][j], xr2[j], acc2[(k + 2) & 3][j]);
#pragma unroll
        for (int j = 0; j < 2; j++)
            acc2[(k + 1) & 3][j] = f2fma(wnv2[3][j], xr2[j], acc2[(k + 1) & 3][j]);

        const bool pub = FIRST ? (k >= 3) : (LAST ? (k < 3) : true);
        if (pub) {
            const int sl = (k + 1) & 3;
            float v0, v1, v2, v3;
            upk(acc2[sl][0], v0, v1); upk(acc2[sl][1], v2, v3);
            float p = silu4(v0, v1, v2, v3, gch[0], gch[1], gch[2], gch[3]);
            p += __shfl_xor_sync(0xffffffffu, p, 1);   // 3-level butterfly
            p += __shfl_xor_sync(0xffffffffu, p, 2);
            p += __shfl_xor_sync(0xffffffffu, p, 4);
            if ((lane & 7) == 0)
                pbuf[8 * c + k - 3][wid * 4 + (lane >> 3)] = p;
        }

        // Mid-chunk refill: slots CB..CB+3 fully consumed by every thread.
        if (k == 3) {
            __syncthreads();
            if (tid == 0)
                issue4<CB>(2 * c + 3, s0, ring_u32, mbar_u32, xrow);
        }
    }
    __syncthreads();   // all threads done reading slots CB+4..CB+7

    if (tid == 0)      // refill the back half: group 2c+4 (base CB+4)
        issue4<(CB + 4) % 12>(2 * c + 4, s0, ring_u32, mbar_u32, xrow);
}

// K1: fused rmsnorm + causal dwconv(W=4) + silu + (p1-p0) dot -> sign/token,
// PLUS the per-batch mask scan, performed inline by the last-finishing block
// of each batch (monotonic counter; replay-safe via mod-128 check).
__global__ void __launch_bounds__(THREADS, 2) score_kernel(
    const float* __restrict__ x, const float* __restrict__ nw,
    const float* __restrict__ cw, const float* __restrict__ pw)
{
    extern __shared__ float4 ring[];    // [12][512] : 96KB
    __shared__ __align__(16) u64   mbars[3];
    __shared__ __align__(16) float rinv_s[8];
    __shared__ __align__(16) float pbuf[TOK][64];  // 8KB score partials
    __shared__ int scan_ws[16];
    __shared__ int s_last;

    const int b    = blockIdx.y;
    const int s0   = blockIdx.x * TOK;
    const int tid  = threadIdx.x;
    const int lane = tid & 31, wid = tid >> 5;
    const int c0   = tid * 4;

    const unsigned ring_u32 = smem_u32(ring);
    const unsigned mbar_u32 = smem_u32(mbars);
    const float*   xrow     = x + (size_t)b * SV * DV;

    if (tid == 0) {
#pragma unroll
        for (int m = 0; m < 3; m++) mbar_init(mbar_u32 + m * 8, 1);
    }
    // Block 0: zero the 3 halo slots (rows 0..2 never TMA-written there).
    if (blockIdx.x == 0) {
#pragma unroll
        for (int t = 0; t < 3; t++)
            sts_zero16(ring_u32 + (unsigned)(tid * 16 + t * 8192));
    }
    __syncthreads();
    if (tid == 0) {
        issue4<0>(0, s0, ring_u32, mbar_u32, xrow);
        issue4<4>(1, s0, ring_u32, mbar_u32, xrow);
        issue4<8>(2, s0, ring_u32, mbar_u32, xrow);
    }

    // Constants: fold nw into conv taps -> wnv[tap][c] = cw[c][tap]*nw[c]
    u64 wnv2[4][2];
    float gch[4];
#pragma unroll
    for (int j = 0; j < 2; j++) {
        int d = c0 + 2 * j;
        float n0 = nw[d], n1 = nw[d + 1];
#pragma unroll
        for (int wi = 0; wi < 4; wi++)
            wnv2[wi][j] = pk(cw[d * 4 + wi] * n0, cw[(d + 1) * 4 + wi] * n1);
    }
#pragma unroll
    for (int c = 0; c < 4; c++) gch[c] = pw[DV + c0 + c] - pw[c0 + c];

    u64 acc2[4][2];
#pragma unroll
    for (int s = 0; s < 4; s++) { acc2[s][0] = 0ull; acc2[s][1] = 0ull; }

    // Chunks 0..4; ring base rotates 0,8,4,0,8 (compile-time).
    process_chunk<0, true , false>(0, s0, tid, lane, wid, ring, ring_u32,
                                   mbar_u32, xrow, acc2, wnv2, gch, rinv_s, pbuf);
    process_chunk<8, false, false>(1, s0, tid, lane, wid, ring, ring_u32,
                                   mbar_u32, xrow, acc2, wnv2, gch, rinv_s, pbuf);
    process_chunk<4, false, false>(2, s0, tid, lane, wid, ring, ring_u32,
                                   mbar_u32, xrow, acc2, wnv2, gch, rinv_s, pbuf);
    process_chunk<0, false, false>(3, s0, tid, lane, wid, ring, ring_u32,
                                   mbar_u32, xrow, acc2, wnv2, gch, rinv_s, pbuf);
    process_chunk<8, false, true >(4, s0, tid, lane, wid, ring, ring_u32,
                                   mbar_u32, xrow, acc2, wnv2, gch, rinv_s, pbuf);

    __syncthreads();
    if (tid < TOK) {
        const float4* sp = (const float4*)pbuf[tid];
        float t = 0.f;
#pragma unroll
        for (int j = 0; j < 16; j++) {
            const float4 v = sp[j];
            t += ((v.x + v.y) + (v.z + v.w));
        }
        g_mask[b * SV + s0 + tid] = (t > 0.f) ? 1 : 0;
    }
    __syncthreads();

    // ---- Fused per-batch scan: last-arriving block of batch b scans it.
    // g_done is monotonic across graph replays; (old & 127) == 127 marks
    // the 128th arrival of THIS launch (128 seq-tiles per batch).
    if (tid == 0) {
        __threadfence();                      // release my mask tile
        unsigned old = atomicAdd(&g_done[b], 1u);
        s_last = ((old & 127u) == 127u) ? 1 : 0;
    }
    __syncthreads();
    if (s_last) {
        __threadfence();                      // acquire all mask tiles
        int* srcb = g_src + b * SV;
        const int base = tid * 8;
#pragma unroll
        for (int j = 0; j < 8; j++) srcb[base + j] = -1;

        const int* mb = g_mask + b * SV;
        int m[8], pre[8], sum = 0;
#pragma unroll
        for (int k = 0; k < 8; k++) {
            m[k] = mb[base + k];
            sum += m[k];
            pre[k] = sum;
        }
        int v = sum;
#pragma unroll
        for (int o = 1; o < 32; o <<= 1) {
            int t = __shfl_up_sync(0xffffffffu, v, o);
            if (lane >= o) v += t;
        }
        if (lane == 31) scan_ws[wid] = v;
        __syncthreads();
        if (wid == 0 && lane < 16) {
            int t = scan_ws[lane];
#pragma unroll
            for (int o = 1; o < 16; o <<= 1) {
                int u = __shfl_up_sync(0x0000ffffu, t, o);
                if (lane >= o) t += u;
            }
            scan_ws[lane] = t;
        }
        __syncthreads();
        const int offset = (wid > 0 ? scan_ws[wid - 1] : 0) + (v - sum);
#pragma unroll
        for (int k = 0; k < 8; k++)
            if (m[k]) srcb[offset + pre[k] - 1] = base + k;
    }
}

// K3: row-wise gather of x (selected, packed) or zero-fill -------------------
__global__ void __launch_bounds__(256) scatter_kernel(
    const float* __restrict__ x, float* __restrict__ out)
{
    const int row = blockIdx.x;              // 0 .. B*S-1
    const int b   = row >> 12;               // S = 4096
    const int s   = g_src[row];
    float4* o = (float4*)(out + (size_t)row * DV) + threadIdx.x;
    if (s >= 0) {
        const float4* xr =
            (const float4*)(x + ((size_t)(b << 12) + s) * DV) + threadIdx.x;
        float4 v0 = __ldcs(xr);
        float4 v1 = __ldcs(xr + 256);
        __stcs(o, v0);
        __stcs(o + 256, v1);
    } else {
        float4 z = make_float4(0.f, 0.f, 0.f, 0.f);
        __stcs(o, z);
        __stcs(o + 256, z);
    }
}

extern "C" void kernel_launch(void* const* d_in, const int* in_sizes, int n_in,
                              void* d_out, int out_size) {
    const float* x  = (const float*)d_in[0];  // [B,S,D]
    const float* nw = (const float*)d_in[1];  // [D]
    const float* cw = (const float*)d_in[2];  // [D,4]
    const float* pw = (const float*)d_in[3];  // [2,D]
    float* out = (float*)d_out;               // [B,S,D]

    const int ring_bytes = 12 * 8192;         // 96KB dynamic smem
    cudaFuncSetAttribute(score_kernel,
                         cudaFuncAttributeMaxDynamicSharedMemorySize,
                         ring_bytes);
    cudaFuncSetAttribute(score_kernel,
                         cudaFuncAttributePreferredSharedMemoryCarveout, 100);

    dim3 g1(SV / TOK, BV);
    score_kernel<<<g1, THREADS, ring_bytes>>>(x, nw, cw, pw);
    scatter_kernel<<<BV * SV, 256>>>(x, out);
}

// round 17
// speedup vs baseline: 1.0327x; 1.0327x over previous
#include <cuda_runtime.h>

// Problem shape (fixed by the dataset): B=4, S=4096, D=2048, W=4
#define BV 4
#define SV 4096
#define DV 2048
#define TOK 32            // tokens per score block
#define NROWS 35          // real rows (3-row causal halo)
#define NGROUP 10         // 4-row TMA groups (rows 0..39, 36..39 pad)
#define THREADS 512       // 4 channels/thread

// Scratch (no allocations allowed) ------------------------------------------
__device__ int g_mask[BV * SV];
__device__ int g_src [BV * SV];

// Packed f32x2 helpers --------------------------------------------------------
typedef unsigned long long u64;
static __device__ __forceinline__ u64 pk(float lo, float hi) {
    u64 r; asm("mov.b64 %0,{%1,%2};" : "=l"(r) : "f"(lo), "f"(hi)); return r;
}
static __device__ __forceinline__ void upk(u64 v, float& lo, float& hi) {
    asm("mov.b64 {%0,%1},%2;" : "=f"(lo), "=f"(hi) : "l"(v));
}
static __device__ __forceinline__ u64 f2fma(u64 a, u64 b, u64 c) {
    u64 d; asm("fma.rn.f32x2 %0,%1,%2,%3;" : "=l"(d) : "l"(a), "l"(b), "l"(c)); return d;
}
static __device__ __forceinline__ u64 f2mul(u64 a, u64 b) {
    u64 d; asm("mul.rn.f32x2 %0,%1,%2;" : "=l"(d) : "l"(a), "l"(b)); return d;
}

static __device__ __forceinline__ float warp_sum(float v) {
#pragma unroll
    for (int o = 16; o > 0; o >>= 1)
        v += __shfl_xor_sync(0xffffffffu, v, o);
    return v;
}

// Bulk-copy + mbarrier helpers ------------------------------------------------
static __device__ __forceinline__ unsigned smem_u32(const void* p) {
    unsigned long long g;
    asm("cvta.to.shared.u64 %0, %1;" : "=l"(g) : "l"(p));
    return (unsigned)g;
}
static __device__ __forceinline__ void mbar_init(unsigned mbar, unsigned cnt) {
    asm volatile("mbarrier.init.shared.b64 [%0], %1;" :: "r"(mbar), "r"(cnt)
                 : "memory");
}
static __device__ __forceinline__ void mbar_expect_tx(unsigned mbar,
                                                      unsigned bytes) {
    asm volatile("mbarrier.arrive.expect_tx.shared.b64 _, [%0], %1;"
                 :: "r"(mbar), "r"(bytes) : "memory");
}
static __device__ __forceinline__ void mbar_wait(unsigned mbar,
                                                 unsigned parity) {
    asm volatile(
        "{\n\t.reg .pred P;\n\t"
        "WAIT_%=:\n\t"
        "mbarrier.try_wait.parity.acquire.cta.shared::cta.b64 P, [%0], %1, 0x989680;\n\t"
        "@!P bra WAIT_%=;\n\t"
        "}"
        :: "r"(mbar), "r"(parity) : "memory");
}
static __device__ __forceinline__ void bulk_g2s(unsigned dst, const void* src,
                                                unsigned mbar) {
    asm volatile(
        "cp.async.bulk.shared::cluster.global.mbarrier::complete_tx::bytes "
        "[%0], [%1], %2, [%3];"
        :: "r"(dst), "l"(src), "r"(8192u), "r"(mbar) : "memory");
}
static __device__ __forceinline__ void sts_zero16(unsigned dst) {
    asm volatile("st.shared.v4.b32 [%0],{%1,%1,%1,%1};" :: "r"(dst), "r"(0));
}

// Sum of 4 silu-gated terms with ONE reciprocal
static __device__ __forceinline__ float silu4(
    float v0, float v1, float v2, float v3,
    float g0, float g1, float g2, float g3)
{
    float d0 = 1.f + __expf(-v0);
    float d1 = 1.f + __expf(-v1);
    float d2 = 1.f + __expf(-v2);
    float d3 = 1.f + __expf(-v3);
    float a0 = g0 * v0, a1 = g1 * v1, a2 = g2 * v2, a3 = g3 * v3;
    float n01 = fmaf(a0, d1, a1 * d0);
    float n23 = fmaf(a2, d3, a3 * d2);
    float D01 = d0 * d1;
    float D23 = d2 * d3;
    float n = fmaf(n01, D23, n23 * D01);
    float D = D01 * D23;
    return __fdividef(n, D);
}

// Issue a 4-row TMA group. GB = (4g) % 12 compile-time; mbar = GB/4.
template<int GB>
static __device__ __forceinline__ void issue4(int g, int s0,
                                              unsigned ring_u32,
                                              unsigned mbar_u32,
                                              const float* xrow) {
    if (g >= NGROUP) return;
    const unsigned mbar = mbar_u32 + (GB / 4) * 8;
    int cnt = 0;
#pragma unroll
    for (int k = 0; k < 4; k++) {
        const int i = 4 * g + k;
        if (i < NROWS && (s0 - 3 + i) >= 0) cnt++;
    }
    mbar_expect_tx(mbar, (unsigned)cnt * 8192u);
#pragma unroll
    for (int k = 0; k < 4; k++) {
        const int i = 4 * g + k;
        if (i < NROWS && (s0 - 3 + i) >= 0)
            bulk_g2s(ring_u32 + (unsigned)((GB + k) * 8192),
                     xrow + (size_t)(s0 - 3 + i) * DV, mbar);
    }
}

// One 8-row chunk (512 threads, 4 ch/thread). CB = (8c)%12 in {0,8,4}.
// Split waits: warps 0-3 wait only the even group, warps 4-7 only the odd
// group, warps 8-15 wait on nothing (the post-Phase-A __syncthreads joins
// and fences before anyone reads in Phase B). Mid-chunk TMA issue (after
// k=3) keeps the odd group half a chunk ahead.
template<int CB, bool FIRST, bool LAST>
static __device__ __forceinline__ void process_chunk(
    int c, int s0, int tid, int lane, int wid,
    const float4* ring, unsigned ring_u32, unsigned mbar_u32,
    const float* xrow, u64 (&acc2)[4][2], const u64 (&wnv2)[4][2],
    const float (&gch)[4], float* rinv_s, float (*pbuf)[64])
{
    constexpr int M0 = (CB == 0) ? 0 : ((CB == 8) ? 2 : 1);   // (2c)%3
    constexpr int M1 = (CB == 0) ? 1 : ((CB == 8) ? 0 : 2);   // (2c+1)%3

    // ---- Phase A: per-warp wait + warp-per-row rinv (FFMA2 sumsq)
    if (wid < 8) {
        if (wid < 4) mbar_wait(mbar_u32 + M0 * 8, (unsigned)(((2 * c)     / 3) & 1));
        else         mbar_wait(mbar_u32 + M1 * 8, (unsigned)(((2 * c + 1) / 3) & 1));

        if (!LAST || wid < 3) {
            int slot = CB + wid; if (slot >= 12) slot -= 12;
            const float4* rowp = ring + slot * 512;
            u64 sa = 0ull, sb = 0ull;
#pragma unroll
            for (int j = 0; j < 16; j++) {
                const float4 v = rowp[lane + 32 * j];
                const u64 p0 = pk(v.x, v.y), p1 = pk(v.z, v.w);
                sa = f2fma(p0, p0, sa);
                sb = f2fma(p1, p1, sb);
            }
            float a0, a1, b0, b1;
            upk(sa, a0, a1); upk(sb, b0, b1);
            float ss = warp_sum((a0 + a1) + (b0 + b1));
            if (lane == 0) rinv_s[wid] = rsqrtf(ss * (1.f / DV) + 1e-5f);
        }
    }
    __syncthreads();   // joins waits + publishes rinv_s + TMA data to all

    float rv[8];
    {
        const float4 r0 = *(const float4*)rinv_s;
        const float4 r1 = *(const float4*)(rinv_s + 4);
        rv[0] = r0.x; rv[1] = r0.y; rv[2] = r0.z; rv[3] = r0.w;
        rv[4] = r1.x; rv[5] = r1.y; rv[6] = r1.z; rv[7] = r1.w;
    }

    // ---- Phase B: branch-free conv/silu/dot (slots compile-time)
#pragma unroll
    for (int k = 0; k < 8; k++) {
        const float4 a = ring[((CB + k) % 12) * 512 + tid];
        const u64 ri2 = pk(rv[k], rv[k]);
        u64 xr2[2] = { f2mul(ri2, pk(a.x, a.y)), f2mul(ri2, pk(a.z, a.w)) };

#pragma unroll
        for (int j = 0; j < 2; j++)          // tap0 OVERWRITES (no resets)
            acc2[k & 3][j] = f2mul(wnv2[0][j], xr2[j]);
#pragma unroll
        for (int j = 0; j < 2; j++)
            acc2[(k + 3) & 3][j] = f2fma(wnv2[1][j], xr2[j], acc2[(k + 3) & 3][j]);
#pragma unroll
        for (int j = 0; j < 2; j++)
            acc2[(k + 2) & 3][j] = f2fma(wnv2[2][j], xr2[j], acc2[(k + 2) & 3][j]);
#pragma unroll
        for (int j = 0; j < 2; j++)
            acc2[(k + 1) & 3][j] = f2fma(wnv2[3][j], xr2[j], acc2[(k + 1) & 3][j]);

        const bool pub = FIRST ? (k >= 3) : (LAST ? (k < 3) : true);
        if (pub) {
            const int sl = (k + 1) & 3;
            float v0, v1, v2, v3;
            upk(acc2[sl][0], v0, v1); upk(acc2[sl][1], v2, v3);
            float p = silu4(v0, v1, v2, v3, gch[0], gch[1], gch[2], gch[3]);
            p += __shfl_xor_sync(0xffffffffu, p, 1);   // 3-level butterfly
            p += __shfl_xor_sync(0xffffffffu, p, 2);
            p += __shfl_xor_sync(0xffffffffu, p, 4);
            if ((lane & 7) == 0)
                pbuf[8 * c + k - 3][wid * 4 + (lane >> 3)] = p;
        }

        // Mid-chunk refill: slots CB..CB+3 fully consumed by every thread.
        if (k == 3) {
            __syncthreads();
            if (tid == 0)
                issue4<CB>(2 * c + 3, s0, ring_u32, mbar_u32, xrow);
        }
    }
    __syncthreads();   // all threads done reading slots CB+4..CB+7

    if (tid == 0)      // refill the back half: group 2c+4 (base CB+4)
        issue4<(CB + 4) % 12>(2 * c + 4, s0, ring_u32, mbar_u32, xrow);
}

// K1: fused rmsnorm + causal dwconv(W=4) + silu + (p1-p0) dot -> sign/token.
__global__ void __launch_bounds__(THREADS, 2) score_kernel(
    const float* __restrict__ x, const float* __restrict__ nw,
    const float* __restrict__ cw, const float* __restrict__ pw)
{
    extern __shared__ float4 ring[];    // [12][512] : 96KB
    __shared__ __align__(16) u64   mbars[3];
    __shared__ __align__(16) float rinv_s[8];
    __shared__ __align__(16) float pbuf[TOK][64];  // 8KB score partials

    const int b    = blockIdx.y;
    const int s0   = blockIdx.x * TOK;
    const int tid  = threadIdx.x;
    const int lane = tid & 31, wid = tid >> 5;
    const int c0   = tid * 4;

    const unsigned ring_u32 = smem_u32(ring);
    const unsigned mbar_u32 = smem_u32(mbars);
    const float*   xrow     = x + (size_t)b * SV * DV;

    if (tid == 0) {
#pragma unroll
        for (int m = 0; m < 3; m++) mbar_init(mbar_u32 + m * 8, 1);
    }
    // Block 0: zero the 3 halo slots (rows 0..2 never TMA-written there).
    if (blockIdx.x == 0) {
#pragma unroll
        for (int t = 0; t < 3; t++)
            sts_zero16(ring_u32 + (unsigned)(tid * 16 + t * 8192));
    }
    __syncthreads();
    if (tid == 0) {
        issue4<0>(0, s0, ring_u32, mbar_u32, xrow);
        issue4<4>(1, s0, ring_u32, mbar_u32, xrow);
        issue4<8>(2, s0, ring_u32, mbar_u32, xrow);
    }

    // Constants: fold nw into conv taps -> wnv[tap][c] = cw[c][tap]*nw[c]
    u64 wnv2[4][2];
    float gch[4];
#pragma unroll
    for (int j = 0; j < 2; j++) {
        int d = c0 + 2 * j;
        float n0 = nw[d], n1 = nw[d + 1];
#pragma unroll
        for (int wi = 0; wi < 4; wi++)
            wnv2[wi][j] = pk(cw[d * 4 + wi] * n0, cw[(d + 1) * 4 + wi] * n1);
    }
#pragma unroll
    for (int c = 0; c < 4; c++) gch[c] = pw[DV + c0 + c] - pw[c0 + c];

    u64 acc2[4][2];
#pragma unroll
    for (int s = 0; s < 4; s++) { acc2[s][0] = 0ull; acc2[s][1] = 0ull; }

    // Chunks 0..4; ring base rotates 0,8,4,0,8 (compile-time).
    process_chunk<0, true , false>(0, s0, tid, lane, wid, ring, ring_u32,
                                   mbar_u32, xrow, acc2, wnv2, gch, rinv_s, pbuf);
    process_chunk<8, false, false>(1, s0, tid, lane, wid, ring, ring_u32,
                                   mbar_u32, xrow, acc2, wnv2, gch, rinv_s, pbuf);
    process_chunk<4, false, false>(2, s0, tid, lane, wid, ring, ring_u32,
                                   mbar_u32, xrow, acc2, wnv2, gch, rinv_s, pbuf);
    process_chunk<0, false, false>(3, s0, tid, lane, wid, ring, ring_u32,
                                   mbar_u32, xrow, acc2, wnv2, gch, rinv_s, pbuf);
    process_chunk<8, false, true >(4, s0, tid, lane, wid, ring, ring_u32,
                                   mbar_u32, xrow, acc2, wnv2, gch, rinv_s, pbuf);

    __syncthreads();
    if (tid < TOK) {
        const float4* sp = (const float4*)pbuf[tid];
        float t = 0.f;
#pragma unroll
        for (int j = 0; j < 16; j++) {
            const float4 v = sp[j];
            t += ((v.x + v.y) + (v.z + v.w));
        }
        g_mask[b * SV + s0 + tid] = (t > 0.f) ? 1 : 0;
    }
}

// K2: per-batch inclusive scan of masks -> inverse map src[b][c-1] = s -------
__global__ void __launch_bounds__(1024) scan_kernel() {
    const int b   = blockIdx.x;
    const int tid = threadIdx.x;
    for (int j = tid; j < SV; j += 1024) g_src[b * SV + j] = -1;
    __syncthreads();

    int base = tid * 4;
    int m[4], pre[4];
    int sum = 0;
#pragma unroll
    for (int k = 0; k < 4; k++) {
        m[k] = g_mask[b * SV + base + k];
        sum += m[k];
        pre[k] = sum;
    }
    int lane = tid & 31, wid = tid >> 5;
    int v = sum;
#pragma unroll
    for (int o = 1; o < 32; o <<= 1) {
        int t = __shfl_up_sync(0xffffffffu, v, o);
        if (lane >= o) v += t;
    }
    __shared__ int wsum[32];
    if (lane == 31) wsum[wid] = v;
    __syncthreads();
    if (wid == 0) {
        int t = wsum[lane];
#pragma unroll
        for (int o = 1; o < 32; o <<= 1) {
            int u = __shfl_up_sync(0xffffffffu, t, o);
            if (lane >= o) t += u;
        }
        wsum[lane] = t;
    }
    __syncthreads();
    int offset = (wid > 0 ? wsum[wid - 1] : 0) + (v - sum);
#pragma unroll
    for (int k = 0; k < 4; k++) {
        if (m[k]) g_src[b * SV + offset + pre[k] - 1] = base + k;
    }
}

// K3: row-wise gather of x (selected, packed) or zero-fill -------------------
__global__ void __launch_bounds__(256) scatter_kernel(
    const float* __restrict__ x, float* __restrict__ out)
{
    const int row = blockIdx.x;              // 0 .. B*S-1
    const int b   = row >> 12;               // S = 4096
    const int s   = g_src[row];
    float4* o = (float4*)(out + (size_t)row * DV) + threadIdx.x;
    if (s >= 0) {
        const float4* xr =
            (const float4*)(x + ((size_t)(b << 12) + s) * DV) + threadIdx.x;
        float4 v0 = __ldcs(xr);
        float4 v1 = __ldcs(xr + 256);
        __stcs(o, v0);
        __stcs(o + 256, v1);
    } else {
        float4 z = make_float4(0.f, 0.f, 0.f, 0.f);
        __stcs(o, z);
        __stcs(o + 256, z);
    }
}

extern "C" void kernel_launch(void* const* d_in, const int* in_sizes, int n_in,
                              void* d_out, int out_size) {
    const float* x  = (const float*)d_in[0];  // [B,S,D]
    const float* nw = (const float*)d_in[1];  // [D]
    const float* cw = (const float*)d_in[2];  // [D,4]
    const float* pw = (const float*)d_in[3];  // [2,D]
    float* out = (float*)d_out;               // [B,S,D]

    const int ring_bytes = 12 * 8192;         // 96KB dynamic smem
    cudaFuncSetAttribute(score_kernel,
                         cudaFuncAttributeMaxDynamicSharedMemorySize,
                         ring_bytes);
    cudaFuncSetAttribute(score_kernel,
                         cudaFuncAttributePreferredSharedMemoryCarveout, 100);

    dim3 g1(SV / TOK, BV);
    score_kernel<<<g1, THREADS, ring_bytes>>>(x, nw, cw, pw);
    scan_kernel<<<BV, 1024>>>();
    scatter_kernel<<<BV * SV, 256>>>(x, out);
}